// round 10
// baseline (speedup 1.0000x reference)
#include <cuda_runtime.h>
#include <cuda_bf16.h>
#include <cstdint>

#define BATCH 64
#define NPTS  50176
#define KC    16
#define NBUCK 2048
#define CAP2  512
#define CAP1  2048
#define T2TH  (1u << 24)
#define NCHUNK 28
#define PPB    1792
#define ATHREADS 128
#define PPT    14
#define GCHUNK 6272
#define ITERS  10

// ---------------- device scratch (no allocations allowed) ----------------
__device__ unsigned           g_bits1[(size_t)BATCH * NPTS];
__device__ unsigned           g_hist[BATCH][NBUCK];
__device__ unsigned long long g_cand2[BATCH][CAP2];
__device__ int                g_c2cnt[BATCH];
__device__ float              g_cent[BATCH][KC][3];
__device__ float              g_part[2][BATCH][NCHUNK][64];

// ---------------- threefry2x32 core ----------------
__device__ __forceinline__ uint2 tf2x32(unsigned k0, unsigned k1,
                                        unsigned x0, unsigned x1) {
  unsigned ks2 = k0 ^ k1 ^ 0x1BD11BDAu;
  x0 += k0; x1 += k1;
#define TFR(r) { x0 += x1; x1 = (x1 << (r)) | (x1 >> (32 - (r))); x1 ^= x0; }
  TFR(13) TFR(15) TFR(26) TFR(6)
  x0 += k1;  x1 += ks2 + 1u;
  TFR(17) TFR(29) TFR(16) TFR(24)
  x0 += ks2; x1 += k0 + 2u;
  TFR(13) TFR(15) TFR(26) TFR(6)
  x0 += k0;  x1 += k1 + 3u;
  TFR(17) TFR(29) TFR(16) TFR(24)
  x0 += k1;  x1 += ks2 + 4u;
  TFR(13) TFR(15) TFR(26) TFR(6)
  x0 += ks2; x1 += k0 + 5u;
#undef TFR
  uint2 r; r.x = x0; r.y = x1; return r;
}

// PARTITIONABLE threefry (jax default since 0.4.36).
__device__ __forceinline__ void batch_subkeys(int b, unsigned &s10, unsigned &s11,
                                              unsigned &s20, unsigned &s21) {
  uint2 kb   = tf2x32(0u, 42u, 0u, (unsigned)b);
  uint2 key1 = tf2x32(kb.x, kb.y, 0u, 0u);
  uint2 sub1 = tf2x32(kb.x, kb.y, 0u, 1u);
  s10 = sub1.x; s11 = sub1.y;
  uint2 sub2 = tf2x32(key1.x, key1.y, 0u, 1u);
  s20 = sub2.x; s21 = sub2.y;
}

// ---------------- init / bit generation / selection (proven, frozen) --------
__global__ void init_k() {
  int b = blockIdx.x, tid = threadIdx.x;
  for (int i = tid; i < NBUCK; i += 256) g_hist[b][i] = 0u;
  if (tid == 0) g_c2cnt[b] = 0;
}

__global__ void gen_k() {
  __shared__ unsigned sh[NBUCK];
  int b = blockIdx.y, ch = blockIdx.x, tid = threadIdx.x;
  for (int i = tid; i < NBUCK; i += 256) sh[i] = 0u;
  unsigned s10, s11, s20, s21;
  batch_subkeys(b, s10, s11, s20, s21);
  __syncthreads();
  unsigned* bb = g_bits1 + (size_t)b * NPTS;
  int m0 = ch * GCHUNK;
  for (int i = m0 + tid; i < m0 + GCHUNK; i += 256) {
    uint2 r1 = tf2x32(s10, s11, 0u, (unsigned)i);
    unsigned w1 = r1.x ^ r1.y;
    bb[i] = w1;
    atomicAdd(&sh[w1 >> 21], 1u);
    uint2 r2 = tf2x32(s20, s21, 0u, (unsigned)i);
    unsigned w2 = r2.x ^ r2.y;
    if (w2 < T2TH) {
      int p = atomicAdd(&g_c2cnt[b], 1);
      if (p < CAP2) g_cand2[b][p] = ((unsigned long long)w2 << 32) | (unsigned)i;
    }
  }
  __syncthreads();
  for (int i = tid; i < NBUCK; i += 256) {
    unsigned c = sh[i];
    if (c) atomicAdd(&g_hist[b][i], c);
  }
}

__global__ void select_k(const float* __restrict__ x) {
  __shared__ unsigned long long sC2[CAP2];
  __shared__ unsigned long long sC1[CAP1];
  __shared__ unsigned sCum[NBUCK + 1];
  __shared__ unsigned sChk[256];
  __shared__ unsigned sJ[KC];
  __shared__ int sTB[KC], sTR[KC];
  __shared__ unsigned char sIsT[NBUCK];
  __shared__ unsigned sPos[KC];
  __shared__ int sC1n;
  int b = blockIdx.x, tid = threadIdx.x;

  int n2 = g_c2cnt[b]; if (n2 > CAP2) n2 = CAP2;
  for (int i = tid; i < n2; i += 256) sC2[i] = g_cand2[b][i];
  unsigned v[8]; unsigned csum = 0;
#pragma unroll
  for (int q = 0; q < 8; q++) { v[q] = g_hist[b][tid * 8 + q]; csum += v[q]; }
  sChk[tid] = csum;
  for (int i = tid; i < NBUCK; i += 256) sIsT[i] = 0;
  if (tid == 0) sC1n = 0;
  __syncthreads();

  for (int i = tid; i < n2; i += 256) {
    unsigned long long key = sC2[i];
    int rk = 0;
    for (int j = 0; j < n2; j++) rk += (sC2[j] < key);
    if (rk < KC) sJ[rk] = (unsigned)(key & 0xffffffffu);
  }
  if (tid == 0) {
    unsigned run = 0;
    for (int t = 0; t < 256; t++) { unsigned c = sChk[t]; sChk[t] = run; run += c; }
  }
  __syncthreads();

  {
    unsigned run = sChk[tid];
#pragma unroll
    for (int q = 0; q < 8; q++) { sCum[tid * 8 + q] = run; run += v[q]; }
    if (tid == 255) sCum[NBUCK] = run;
  }
  __syncthreads();

  if (tid < KC) {
    unsigned j = sJ[tid];
    int lo = 0, hi = NBUCK;
    while (hi - lo > 1) { int mid = (lo + hi) >> 1; if (sCum[mid] <= j) lo = mid; else hi = mid; }
    sTB[tid] = lo;
    sTR[tid] = (int)(j - sCum[lo]);
    sIsT[lo] = 1;
  }
  __syncthreads();

  const unsigned* bb = g_bits1 + (size_t)b * NPTS;
  for (int i = tid; i < NPTS; i += 256) {
    unsigned w = bb[i];
    if (sIsT[w >> 21]) {
      int p = atomicAdd(&sC1n, 1);
      if (p < CAP1) sC1[p] = ((unsigned long long)w << 32) | (unsigned)i;
    }
  }
  __syncthreads();

  int M = sC1n; if (M > CAP1) M = CAP1;
  for (int i = tid; i < M; i += 256) {
    unsigned long long key = sC1[i];
    unsigned bkt = (unsigned)(key >> 53);
    int rk = 0;
    for (int j = 0; j < M; j++) {
      unsigned long long kj = sC1[j];
      rk += (int)(((unsigned)(kj >> 53) == bkt) && (kj < key));
    }
#pragma unroll
    for (int t = 0; t < KC; t++)
      if (sTB[t] == (int)bkt && sTR[t] == rk) sPos[t] = (unsigned)(key & 0xffffffffu);
  }
  __syncthreads();

  if (tid < KC * 3) {
    int t = tid / 3, c = tid % 3;
    g_cent[b][t][c] = x[((size_t)b * NPTS + sPos[t]) * 3 + c];
  }
}

// ---------------- fused centroid-reduce + assignment + accumulation ---------
// k-outer / point-inner: points resident in registers, centroid constants in
// SMEM (broadcast LDS.128 per k). No spills; 14 independent dep-chains.
__global__ void __launch_bounds__(ATHREADS, 5) assign_k(const float* __restrict__ x,
                                                        int iter) {
  __shared__ float4 sAcc[KC][ATHREADS];   // (sx, sy, sz, count), 32 KB
  __shared__ float  sRed[64];
  __shared__ float  sCent[KC][3];
  __shared__ float4 sCst[KC];             // (-2c0, -2c1, -2c2, |c|^2)
  int b = blockIdx.y, ch = blockIdx.x, tid = threadIdx.x;
  int cur = iter & 1, prev = cur ^ 1;

  if (iter == 0) {
    if (tid < KC * 3) ((float*)sCent)[tid] = ((const float*)g_cent[b])[tid];
  } else {
    if (tid < 64) {
      float s = 0.0f;
#pragma unroll
      for (int c2 = 0; c2 < NCHUNK; c2++) s += g_part[prev][b][c2][tid];
      sRed[tid] = s;
    }
    __syncthreads();
    if (tid < KC * 3) {
      int k = tid / 3, r = tid % 3;
      ((float*)sCent)[tid] = sRed[(k << 2) | r] / sRed[(k << 2) | 3];
    }
  }
  __syncthreads();
  if (tid < KC) {
    float c0 = sCent[tid][0], c1 = sCent[tid][1], c2 = sCent[tid][2];
    sCst[tid] = make_float4(-2.0f * c0, -2.0f * c1, -2.0f * c2,
                            c0 * c0 + c1 * c1 + c2 * c2);
  }
#pragma unroll
  for (int k = 0; k < KC; k++) sAcc[k][tid] = make_float4(0.f, 0.f, 0.f, 0.f);
  __syncthreads();

  const float* __restrict__ xb = x + ((size_t)b * NPTS + (size_t)ch * PPB) * 3;
  float X0[PPT], X1[PPT], X2[PPT];
#pragma unroll
  for (int p = 0; p < PPT; p++) {
    int i = p * ATHREADS + tid;
    X0[p] = xb[3 * i + 0]; X1[p] = xb[3 * i + 1]; X2[p] = xb[3 * i + 2];
  }

  float best[PPT]; int bk[PPT];
  {
    float4 c = sCst[0];
#pragma unroll
    for (int p = 0; p < PPT; p++) {
      best[p] = fmaf(X0[p], c.x, fmaf(X1[p], c.y, fmaf(X2[p], c.z, c.w)));
      bk[p] = 0;
    }
  }
#pragma unroll 5
  for (int k = 1; k < KC; k++) {
    float4 c = sCst[k];
#pragma unroll
    for (int p = 0; p < PPT; p++) {
      float d = fmaf(X0[p], c.x, fmaf(X1[p], c.y, fmaf(X2[p], c.z, c.w)));
      bool pr = d < best[p];                 // strict < keeps first-min
      best[p] = pr ? d : best[p];
      bk[p]   = pr ? k : bk[p];
    }
  }

#pragma unroll
  for (int p = 0; p < PPT; p++) {
    float4* a = &sAcc[bk[p]][tid];
    float4 v = *a;
    v.x += X0[p]; v.y += X1[p]; v.z += X2[p]; v.w += 1.0f;
    *a = v;
  }
  __syncthreads();

  int warp = tid >> 5, lane = tid & 31;
  const float* sf = (const float*)sAcc;
  for (int fld = warp; fld < 64; fld += ATHREADS / 32) {
    int k = fld >> 2, r = fld & 3;
    float s = 0.0f;
    for (int j = lane; j < ATHREADS; j += 32) s += sf[(k * ATHREADS + j) * 4 + r];
#pragma unroll
    for (int off = 16; off > 0; off >>= 1) s += __shfl_down_sync(0xffffffffu, s, off);
    if (lane == 0) g_part[cur][b][ch][fld] = s;
  }
}

// Final reduce of the last iteration's partials -> d_out.
__global__ void update_k(float* __restrict__ out) {
  __shared__ float sv[64];
  int b = blockIdx.x, tid = threadIdx.x;   // 64 threads
  float s = 0.0f;
#pragma unroll
  for (int ch = 0; ch < NCHUNK; ch++) s += g_part[(ITERS - 1) & 1][b][ch][tid];
  sv[tid] = s;
  __syncthreads();
  int k = tid >> 2, r = tid & 3;
  if (r < 3) out[b * 48 + k * 3 + r] = sv[(k << 2) | r] / sv[(k << 2) | 3];
}

extern "C" void kernel_launch(void* const* d_in, const int* in_sizes, int n_in,
                              void* d_out, int out_size) {
  (void)in_sizes; (void)n_in; (void)out_size;
  const float* x = (const float*)d_in[0];
  float* out = (float*)d_out;
  init_k<<<BATCH, 256>>>();
  gen_k<<<dim3(8, BATCH), 256>>>();
  select_k<<<BATCH, 256>>>(x);
  for (int it = 0; it < ITERS; it++)
    assign_k<<<dim3(NCHUNK, BATCH), ATHREADS>>>(x, it);
  update_k<<<BATCH, 64>>>(out);
}

// round 11
// speedup vs baseline: 1.0897x; 1.0897x over previous
#include <cuda_runtime.h>
#include <cuda_bf16.h>
#include <cstdint>

#define BATCH 64
#define NPTS  50176
#define KC    16
#define NBUCK 2048
#define CAP2  512
#define CAP1  2048
#define T2TH  (1u << 24)
#define NCHUNK 28
#define PPB    1792
#define ATHREADS 128
#define PPT    14
#define PPAIR  7
#define GCHUNK 6272
#define ITERS  10

// ---------------- device scratch (no allocations allowed) ----------------
__device__ unsigned           g_bits1[(size_t)BATCH * NPTS];
__device__ unsigned           g_hist[BATCH][NBUCK];
__device__ unsigned long long g_cand2[BATCH][CAP2];
__device__ int                g_c2cnt[BATCH];
__device__ float              g_cent[BATCH][KC][3];
__device__ float              g_part[2][BATCH][NCHUNK][64];

// ---------------- packed f32x2 helpers ----------------
typedef unsigned long long u64;
__device__ __forceinline__ u64 pk2(float lo, float hi) {
  u64 r; asm("mov.b64 %0, {%1,%2};" : "=l"(r) : "f"(lo), "f"(hi)); return r;
}
__device__ __forceinline__ void upk2(u64 v, float &lo, float &hi) {
  asm("mov.b64 {%0,%1}, %2;" : "=f"(lo), "=f"(hi) : "l"(v));
}
__device__ __forceinline__ u64 fma2(u64 a, u64 b, u64 c) {
  u64 d; asm("fma.rn.f32x2 %0, %1, %2, %3;" : "=l"(d) : "l"(a), "l"(b), "l"(c));
  return d;
}
// embed cluster index in low 4 mantissa bits (distances bit-identical otherwise)
__device__ __forceinline__ float mang(float d, int k) {
  return __uint_as_float((__float_as_uint(d) & 0xFFFFFFF0u) | (unsigned)k);
}

// ---------------- threefry2x32 core ----------------
__device__ __forceinline__ uint2 tf2x32(unsigned k0, unsigned k1,
                                        unsigned x0, unsigned x1) {
  unsigned ks2 = k0 ^ k1 ^ 0x1BD11BDAu;
  x0 += k0; x1 += k1;
#define TFR(r) { x0 += x1; x1 = (x1 << (r)) | (x1 >> (32 - (r))); x1 ^= x0; }
  TFR(13) TFR(15) TFR(26) TFR(6)
  x0 += k1;  x1 += ks2 + 1u;
  TFR(17) TFR(29) TFR(16) TFR(24)
  x0 += ks2; x1 += k0 + 2u;
  TFR(13) TFR(15) TFR(26) TFR(6)
  x0 += k0;  x1 += k1 + 3u;
  TFR(17) TFR(29) TFR(16) TFR(24)
  x0 += k1;  x1 += ks2 + 4u;
  TFR(13) TFR(15) TFR(26) TFR(6)
  x0 += ks2; x1 += k0 + 5u;
#undef TFR
  uint2 r; r.x = x0; r.y = x1; return r;
}

// PARTITIONABLE threefry (jax default since 0.4.36).
__device__ __forceinline__ void batch_subkeys(int b, unsigned &s10, unsigned &s11,
                                              unsigned &s20, unsigned &s21) {
  uint2 kb   = tf2x32(0u, 42u, 0u, (unsigned)b);
  uint2 key1 = tf2x32(kb.x, kb.y, 0u, 0u);
  uint2 sub1 = tf2x32(kb.x, kb.y, 0u, 1u);
  s10 = sub1.x; s11 = sub1.y;
  uint2 sub2 = tf2x32(key1.x, key1.y, 0u, 1u);
  s20 = sub2.x; s21 = sub2.y;
}

// ---------------- init / bit generation / selection (proven, frozen) --------
__global__ void init_k() {
  int b = blockIdx.x, tid = threadIdx.x;
  for (int i = tid; i < NBUCK; i += 256) g_hist[b][i] = 0u;
  if (tid == 0) g_c2cnt[b] = 0;
}

__global__ void gen_k() {
  __shared__ unsigned sh[NBUCK];
  int b = blockIdx.y, ch = blockIdx.x, tid = threadIdx.x;
  for (int i = tid; i < NBUCK; i += 256) sh[i] = 0u;
  unsigned s10, s11, s20, s21;
  batch_subkeys(b, s10, s11, s20, s21);
  __syncthreads();
  unsigned* bb = g_bits1 + (size_t)b * NPTS;
  int m0 = ch * GCHUNK;
  for (int i = m0 + tid; i < m0 + GCHUNK; i += 256) {
    uint2 r1 = tf2x32(s10, s11, 0u, (unsigned)i);
    unsigned w1 = r1.x ^ r1.y;
    bb[i] = w1;
    atomicAdd(&sh[w1 >> 21], 1u);
    uint2 r2 = tf2x32(s20, s21, 0u, (unsigned)i);
    unsigned w2 = r2.x ^ r2.y;
    if (w2 < T2TH) {
      int p = atomicAdd(&g_c2cnt[b], 1);
      if (p < CAP2) g_cand2[b][p] = ((unsigned long long)w2 << 32) | (unsigned)i;
    }
  }
  __syncthreads();
  for (int i = tid; i < NBUCK; i += 256) {
    unsigned c = sh[i];
    if (c) atomicAdd(&g_hist[b][i], c);
  }
}

__global__ void select_k(const float* __restrict__ x) {
  __shared__ unsigned long long sC2[CAP2];
  __shared__ unsigned long long sC1[CAP1];
  __shared__ unsigned sCum[NBUCK + 1];
  __shared__ unsigned sChk[256];
  __shared__ unsigned sJ[KC];
  __shared__ int sTB[KC], sTR[KC];
  __shared__ unsigned char sIsT[NBUCK];
  __shared__ unsigned sPos[KC];
  __shared__ int sC1n;
  int b = blockIdx.x, tid = threadIdx.x;

  int n2 = g_c2cnt[b]; if (n2 > CAP2) n2 = CAP2;
  for (int i = tid; i < n2; i += 256) sC2[i] = g_cand2[b][i];
  unsigned v[8]; unsigned csum = 0;
#pragma unroll
  for (int q = 0; q < 8; q++) { v[q] = g_hist[b][tid * 8 + q]; csum += v[q]; }
  sChk[tid] = csum;
  for (int i = tid; i < NBUCK; i += 256) sIsT[i] = 0;
  if (tid == 0) sC1n = 0;
  __syncthreads();

  for (int i = tid; i < n2; i += 256) {
    unsigned long long key = sC2[i];
    int rk = 0;
    for (int j = 0; j < n2; j++) rk += (sC2[j] < key);
    if (rk < KC) sJ[rk] = (unsigned)(key & 0xffffffffu);
  }
  if (tid == 0) {
    unsigned run = 0;
    for (int t = 0; t < 256; t++) { unsigned c = sChk[t]; sChk[t] = run; run += c; }
  }
  __syncthreads();

  {
    unsigned run = sChk[tid];
#pragma unroll
    for (int q = 0; q < 8; q++) { sCum[tid * 8 + q] = run; run += v[q]; }
    if (tid == 255) sCum[NBUCK] = run;
  }
  __syncthreads();

  if (tid < KC) {
    unsigned j = sJ[tid];
    int lo = 0, hi = NBUCK;
    while (hi - lo > 1) { int mid = (lo + hi) >> 1; if (sCum[mid] <= j) lo = mid; else hi = mid; }
    sTB[tid] = lo;
    sTR[tid] = (int)(j - sCum[lo]);
    sIsT[lo] = 1;
  }
  __syncthreads();

  const unsigned* bb = g_bits1 + (size_t)b * NPTS;
  for (int i = tid; i < NPTS; i += 256) {
    unsigned w = bb[i];
    if (sIsT[w >> 21]) {
      int p = atomicAdd(&sC1n, 1);
      if (p < CAP1) sC1[p] = ((unsigned long long)w << 32) | (unsigned)i;
    }
  }
  __syncthreads();

  int M = sC1n; if (M > CAP1) M = CAP1;
  for (int i = tid; i < M; i += 256) {
    unsigned long long key = sC1[i];
    unsigned bkt = (unsigned)(key >> 53);
    int rk = 0;
    for (int j = 0; j < M; j++) {
      unsigned long long kj = sC1[j];
      rk += (int)(((unsigned)(kj >> 53) == bkt) && (kj < key));
    }
#pragma unroll
    for (int t = 0; t < KC; t++)
      if (sTB[t] == (int)bkt && sTR[t] == rk) sPos[t] = (unsigned)(key & 0xffffffffu);
  }
  __syncthreads();

  if (tid < KC * 3) {
    int t = tid / 3, c = tid % 3;
    g_cent[b][t][c] = x[((size_t)b * NPTS + sPos[t]) * 3 + c];
  }
}

// ---------------- fused centroid-reduce + assignment + accumulation ---------
// Point-pairs packed into f32x2 registers (fma.rn.f32x2: per-lane rn, distances
// bit-identical to scalar fmaf). Argmin via index-mangled low mantissa bits +
// FMNMX reduction: 1 alu inst per cluster instead of SETP+2SEL.
__global__ void __launch_bounds__(ATHREADS, 5) assign_k(const float* __restrict__ x,
                                                        int iter) {
  __shared__ float4 sAcc[KC][ATHREADS];   // (sx, sy, sz, count), 32 KB
  __shared__ float  sRed[64];
  __shared__ float  sCent[KC][3];
  __shared__ float4 sCst[KC];             // (-2c0, -2c1, -2c2, |c|^2)
  int b = blockIdx.y, ch = blockIdx.x, tid = threadIdx.x;
  int cur = iter & 1, prev = cur ^ 1;

  if (iter == 0) {
    if (tid < KC * 3) ((float*)sCent)[tid] = ((const float*)g_cent[b])[tid];
  } else {
    if (tid < 64) {
      float s = 0.0f;
#pragma unroll
      for (int c2 = 0; c2 < NCHUNK; c2++) s += g_part[prev][b][c2][tid];
      sRed[tid] = s;
    }
    __syncthreads();
    if (tid < KC * 3) {
      int k = tid / 3, r = tid % 3;
      ((float*)sCent)[tid] = sRed[(k << 2) | r] / sRed[(k << 2) | 3];
    }
  }
  __syncthreads();
  if (tid < KC) {
    float c0 = sCent[tid][0], c1 = sCent[tid][1], c2 = sCent[tid][2];
    sCst[tid] = make_float4(-2.0f * c0, -2.0f * c1, -2.0f * c2,
                            c0 * c0 + c1 * c1 + c2 * c2);
  }
#pragma unroll
  for (int k = 0; k < KC; k++) sAcc[k][tid] = make_float4(0.f, 0.f, 0.f, 0.f);
  __syncthreads();

  const float* __restrict__ xb = x + ((size_t)b * NPTS + (size_t)ch * PPB) * 3;
  // load 14 points, pack adjacent pairs (p = 2q, 2q+1)
  u64 X0[PPAIR], X1[PPAIR], X2[PPAIR];
#pragma unroll
  for (int q = 0; q < PPAIR; q++) {
    int ia = (2 * q) * ATHREADS + tid, ib = (2 * q + 1) * ATHREADS + tid;
    X0[q] = pk2(xb[3 * ia + 0], xb[3 * ib + 0]);
    X1[q] = pk2(xb[3 * ia + 1], xb[3 * ib + 1]);
    X2[q] = pk2(xb[3 * ia + 2], xb[3 * ib + 2]);
  }

  float best[PPT];
  {
    float4 c = sCst[0];
    u64 pm0 = pk2(c.x, c.x), pm1 = pk2(c.y, c.y), pm2 = pk2(c.z, c.z),
        pnn = pk2(c.w, c.w);
#pragma unroll
    for (int q = 0; q < PPAIR; q++) {
      u64 t = fma2(X0[q], pm0, fma2(X1[q], pm1, fma2(X2[q], pm2, pnn)));
      float lo, hi; upk2(t, lo, hi);
      best[2 * q] = mang(lo, 0); best[2 * q + 1] = mang(hi, 0);
    }
  }
#pragma unroll
  for (int k = 1; k < KC; k++) {
    float4 c = sCst[k];
    u64 pm0 = pk2(c.x, c.x), pm1 = pk2(c.y, c.y), pm2 = pk2(c.z, c.z),
        pnn = pk2(c.w, c.w);
#pragma unroll
    for (int q = 0; q < PPAIR; q++) {
      u64 t = fma2(X0[q], pm0, fma2(X1[q], pm1, fma2(X2[q], pm2, pnn)));
      float lo, hi; upk2(t, lo, hi);
      best[2 * q]     = fminf(best[2 * q],     mang(lo, k));
      best[2 * q + 1] = fminf(best[2 * q + 1], mang(hi, k));
    }
  }

#pragma unroll
  for (int q = 0; q < PPAIR; q++) {
    float xa0, xb0, xa1, xb1, xa2, xb2;
    upk2(X0[q], xa0, xb0); upk2(X1[q], xa1, xb1); upk2(X2[q], xa2, xb2);
    {
      int bk = (int)(__float_as_uint(best[2 * q]) & 15u);
      float4* a = &sAcc[bk][tid];
      float4 v = *a;
      v.x += xa0; v.y += xa1; v.z += xa2; v.w += 1.0f;
      *a = v;
    }
    {
      int bk = (int)(__float_as_uint(best[2 * q + 1]) & 15u);
      float4* a = &sAcc[bk][tid];
      float4 v = *a;
      v.x += xb0; v.y += xb1; v.z += xb2; v.w += 1.0f;
      *a = v;
    }
  }
  __syncthreads();

  int warp = tid >> 5, lane = tid & 31;
  const float* sf = (const float*)sAcc;
  for (int fld = warp; fld < 64; fld += ATHREADS / 32) {
    int k = fld >> 2, r = fld & 3;
    float s = 0.0f;
    for (int j = lane; j < ATHREADS; j += 32) s += sf[(k * ATHREADS + j) * 4 + r];
#pragma unroll
    for (int off = 16; off > 0; off >>= 1) s += __shfl_down_sync(0xffffffffu, s, off);
    if (lane == 0) g_part[cur][b][ch][fld] = s;
  }
}

// Final reduce of the last iteration's partials -> d_out.
__global__ void update_k(float* __restrict__ out) {
  __shared__ float sv[64];
  int b = blockIdx.x, tid = threadIdx.x;   // 64 threads
  float s = 0.0f;
#pragma unroll
  for (int ch = 0; ch < NCHUNK; ch++) s += g_part[(ITERS - 1) & 1][b][ch][tid];
  sv[tid] = s;
  __syncthreads();
  int k = tid >> 2, r = tid & 3;
  if (r < 3) out[b * 48 + k * 3 + r] = sv[(k << 2) | r] / sv[(k << 2) | 3];
}

extern "C" void kernel_launch(void* const* d_in, const int* in_sizes, int n_in,
                              void* d_out, int out_size) {
  (void)in_sizes; (void)n_in; (void)out_size;
  const float* x = (const float*)d_in[0];
  float* out = (float*)d_out;
  init_k<<<BATCH, 256>>>();
  gen_k<<<dim3(8, BATCH), 256>>>();
  select_k<<<BATCH, 256>>>(x);
  for (int it = 0; it < ITERS; it++)
    assign_k<<<dim3(NCHUNK, BATCH), ATHREADS>>>(x, it);
  update_k<<<BATCH, 64>>>(out);
}